// round 1
// baseline (speedup 1.0000x reference)
#include <cuda_runtime.h>
#include <math.h>

#define B 16
#define I_IN 256
#define H 512
#define O_OUT 256
#define A 1024
#define M 64
#define R 4
#define IFW 471
#define N4H 2048
#define NCOLS3 (IFW + O_OUT)   // 727

// interface offsets
#define OFF_KR     0
#define OFF_BETAR  256
#define OFF_KW     260
#define OFF_BETAW  324
#define OFF_ERASE  325
#define OFF_WRITEV 389
#define OFF_FREE   453
#define OFF_GA     457
#define OFF_GW     458
#define OFF_PI     459

// ----------------- device scratch (no allocations allowed) -----------------
__device__ float g_zpart[8][B][N4H];
__device__ float g_h[B][H];
__device__ float g_ifpart[4][B][NCOLS3];
__device__ float g_iface[B][IFW];
__device__ float g_outhid[B][O_OUT];
__device__ float g_cwlog[B][A];
__device__ float g_ww[B][A];
__device__ float g_S[B][R];
__device__ float g_T[B][R];
__device__ float g_mem[B][A][M];
__device__ float g_cr[B][R][A];
__device__ float g_P[B][R][A];
__device__ float g_Q[B][R][A];
__device__ float g_Up[8][B][R][A];
__device__ float g_Vp[8][B][R][A];
__device__ float g_rvpart[4][B][R * M];

__device__ __forceinline__ float sigf(float x) { return 1.f / (1.f + __expf(-x)); }
__device__ __forceinline__ float oneplusf(float x) {
    // 1 + softplus(x)
    return 1.f + (x > 20.f ? x : log1pf(__expf(x)));
}

template <int NT>
__device__ __forceinline__ float blockSum(float v, float* s_red) {
    int lane = threadIdx.x & 31, w = threadIdx.x >> 5;
#pragma unroll
    for (int o = 16; o; o >>= 1) v += __shfl_down_sync(0xffffffffu, v, o);
    if (lane == 0) s_red[w] = v;
    __syncthreads();
    if (w == 0) {
        float x = (lane < NT / 32) ? s_red[lane] : 0.f;
#pragma unroll
        for (int o = 16; o; o >>= 1) x += __shfl_down_sync(0xffffffffu, x, o);
        if (lane == 0) s_red[0] = x;
    }
    __syncthreads();
    float res = s_red[0];
    __syncthreads();
    return res;
}

template <int NT>
__device__ __forceinline__ float blockMax(float v, float* s_red) {
    int lane = threadIdx.x & 31, w = threadIdx.x >> 5;
#pragma unroll
    for (int o = 16; o; o >>= 1) v = fmaxf(v, __shfl_down_sync(0xffffffffu, v, o));
    if (lane == 0) s_red[w] = v;
    __syncthreads();
    if (w == 0) {
        float x = (lane < NT / 32) ? s_red[lane] : -1e30f;
#pragma unroll
        for (int o = 16; o; o >>= 1) x = fmaxf(x, __shfl_down_sync(0xffffffffu, x, o));
        if (lane == 0) s_red[0] = x;
    }
    __syncthreads();
    float res = s_red[0];
    __syncthreads();
    return res;
}

// ----------------- K1: z partial GEMM (k-split over 8 chunks) -----------------
__global__ void k1_zpart(const float* __restrict__ x, const float* __restrict__ h_prev,
                         const float* __restrict__ rv_prev, const float* __restrict__ Wx,
                         const float* __restrict__ Wh) {
    __shared__ float s_in[B][128];
    int tid = threadIdx.x;
    int nbase = blockIdx.x * 256;
    int kc = blockIdx.y;
    int kbase = kc * 128;
    for (int idx = tid; idx < B * 128; idx += 256) {
        int b = idx >> 7, kl = idx & 127;
        int kk = kbase + kl;
        float v;
        if (kk < 256) v = x[b * I_IN + kk];
        else if (kk < 512) v = rv_prev[b * 256 + (kk - 256)];
        else v = h_prev[b * H + (kk - 512)];
        s_in[b][kl] = v;
    }
    __syncthreads();
    int n = nbase + tid;
    const float* W = (kbase < 512) ? (Wx + (size_t)kbase * N4H) : (Wh + (size_t)(kbase - 512) * N4H);
    float acc[B];
#pragma unroll
    for (int b = 0; b < B; b++) acc[b] = 0.f;
#pragma unroll 4
    for (int kl = 0; kl < 128; kl++) {
        float w = W[(size_t)kl * N4H + n];
#pragma unroll
        for (int b = 0; b < B; b++) acc[b] = fmaf(w, s_in[b][kl], acc[b]);
    }
#pragma unroll
    for (int b = 0; b < B; b++) g_zpart[kc][b][n] = acc[b];
}

// ----------------- K2: reduce z partials + LSTM elementwise -----------------
__global__ void k2_lstm(const float* __restrict__ c_prev, const float* __restrict__ b_lstm) {
    int idx = blockIdx.x * blockDim.x + threadIdx.x;  // over B*H
    if (idx >= B * H) return;
    int b = idx >> 9, hh = idx & 511;
    float zv[4];
#pragma unroll
    for (int g = 0; g < 4; g++) {
        int n = g * H + hh;
        float s = b_lstm[n];
#pragma unroll
        for (int kc = 0; kc < 8; kc++) s += g_zpart[kc][b][n];
        zv[g] = s;
    }
    float c = sigf(zv[1]) * c_prev[idx] + sigf(zv[0]) * tanhf(zv[2]);
    float h = sigf(zv[3]) * tanhf(c);
    g_h[b][hh] = h;
}

// ----------------- K3: iface + out_hidden partial GEMM -----------------
__global__ void k3_ifpart(const float* __restrict__ W_if, const float* __restrict__ W_hid) {
    int idx = blockIdx.x * 256 + threadIdx.x;
    if (idx >= B * NCOLS3) return;
    int col = idx % NCOLS3, b = idx / NCOLS3;
    int kbase = blockIdx.y * 128;
    const float* hrow = g_h[b] + kbase;
    float acc = 0.f;
    if (col < IFW) {
        const float* W = W_if + (size_t)kbase * IFW + col;
#pragma unroll 8
        for (int k = 0; k < 128; k++) acc = fmaf(hrow[k], W[(size_t)k * IFW], acc);
    } else {
        int c2 = col - IFW;
        const float* W = W_hid + (size_t)kbase * O_OUT + c2;
#pragma unroll 8
        for (int k = 0; k < 128; k++) acc = fmaf(hrow[k], W[(size_t)k * O_OUT], acc);
    }
    g_ifpart[blockIdx.y][b][col] = acc;
}

__global__ void k3b_ifsum(const float* __restrict__ b_if, const float* __restrict__ b_hid) {
    int idx = blockIdx.x * 256 + threadIdx.x;
    if (idx >= B * NCOLS3) return;
    int col = idx % NCOLS3, b = idx / NCOLS3;
    float s = g_ifpart[0][b][col] + g_ifpart[1][b][col] + g_ifpart[2][b][col] + g_ifpart[3][b][col];
    if (col < IFW) g_iface[b][col] = s + b_if[col];
    else g_outhid[b][col - IFW] = s + b_hid[col - IFW];
}

// ----------------- K4a: c_w content logits (on mem_prev), coalesced -----------------
__global__ void k4a_cwlog(const float* __restrict__ mem_prev) {
    int b = blockIdx.y, chunk = blockIdx.x;  // 8 chunks of 128 rows
    int tid = threadIdx.x;                   // 256 = 8 warps
    int warp = tid >> 5, lane = tid & 31;
    __shared__ float s_kw[M];
    __shared__ float s_bw;
    if (tid < M) s_kw[tid] = g_iface[b][OFF_KW + tid];
    if (tid == 0) s_bw = oneplusf(g_iface[b][OFF_BETAW]);
    __syncthreads();
    float kn2 = 0.f;
#pragma unroll
    for (int m = 0; m < M; m++) { float v = s_kw[m]; kn2 = fmaf(v, v, kn2); }
    float knorm = sqrtf(kn2);
    float betaw = s_bw;
    for (int rr = 0; rr < 16; rr++) {
        int a = chunk * 128 + warp * 16 + rr;
        const float2 v = *reinterpret_cast<const float2*>(
            mem_prev + ((size_t)(b * A + a)) * M + lane * 2);
        int m0 = lane * 2;
        float d = v.x * s_kw[m0] + v.y * s_kw[m0 + 1];
        float n = v.x * v.x + v.y * v.y;
#pragma unroll
        for (int o = 16; o; o >>= 1) {
            d += __shfl_down_sync(0xffffffffu, d, o);
            n += __shfl_down_sync(0xffffffffu, n, o);
        }
        if (lane == 0) g_cwlog[b][a] = betaw * d / (knorm * sqrtf(n) + 1e-6f);
    }
}

// ----------------- K4: usage, sort, alloc, c_w softmax, ww, S_r, T_r -----------------
__global__ void k4_alloc_ww(const float* __restrict__ rw_prev, const float* __restrict__ ww_prev,
                            const float* __restrict__ usage_prev,
                            const float* __restrict__ prec_prev) {
    int b = blockIdx.x;
    int tid = threadIdx.x;  // 512
    __shared__ float s_val[A];
    __shared__ float s_tmp[A];
    __shared__ int   s_idx[A];
    __shared__ float s_cw[A];
    __shared__ float s_red[16];
    __shared__ float s_scal[8];
    if (tid == 0) {
        s_scal[1] = sigf(g_iface[b][OFF_GA]);
        s_scal[2] = sigf(g_iface[b][OFF_GW]);
    }
    if (tid < R) s_scal[4 + tid] = sigf(g_iface[b][OFF_FREE + tid]);
    __syncthreads();

    // usage update
    for (int ii = 0; ii < 2; ii++) {
        int a = tid + ii * 512;
        float psi = 1.f;
#pragma unroll
        for (int r = 0; r < R; r++)
            psi *= (1.f - s_scal[4 + r] * rw_prev[(b * R + r) * A + a]);
        float u = usage_prev[b * A + a], w = ww_prev[b * A + a];
        s_val[a] = (u + w - u * w) * psi;
        s_idx[a] = a;
    }
    __syncthreads();

    // bitonic sort ascending, payload = original index
    for (int k = 2; k <= A; k <<= 1) {
        for (int j = k >> 1; j > 0; j >>= 1) {
            for (int i = tid; i < A; i += 512) {
                int l = i ^ j;
                if (l > i) {
                    bool up = ((i & k) == 0);
                    float vi = s_val[i], vl = s_val[l];
                    if ((vi > vl) == up) {
                        s_val[i] = vl; s_val[l] = vi;
                        int t = s_idx[i]; s_idx[i] = s_idx[l]; s_idx[l] = t;
                    }
                }
            }
            __syncthreads();
        }
    }
    float su0 = s_val[tid], su1 = s_val[tid + 512];

    // inclusive cumprod scan (Hillis-Steele, 10 steps -> result back in s_val)
    {
        float* src = s_val;
        float* dst = s_tmp;
        for (int off = 1; off < A; off <<= 1) {
            for (int i = tid; i < A; i += 512)
                dst[i] = (i >= off) ? src[i - off] * src[i] : src[i];
            __syncthreads();
            float* t = src; src = dst; dst = t;
        }
    }
    // allocation weights, scattered back to original positions (into s_tmp)
    {
        float cpe0 = (tid == 0) ? 1.f : s_val[tid - 1];
        float cpe1 = s_val[tid + 511];
        s_tmp[s_idx[tid]]       = (1.f - su0) * cpe0;
        s_tmp[s_idx[tid + 512]] = (1.f - su1) * cpe1;
    }
    __syncthreads();

    // c_w softmax over A
    float l0 = g_cwlog[b][tid], l1 = g_cwlog[b][tid + 512];
    float mx = blockMax<512>(fmaxf(l0, l1), s_red);
    float e0 = __expf(l0 - mx), e1 = __expf(l1 - mx);
    float ssum = blockSum<512>(e0 + e1, s_red);
    float inv = 1.f / ssum;
    s_cw[tid] = e0 * inv;
    s_cw[tid + 512] = e1 * inv;
    __syncthreads();

    // ww + S_r, T_r partials
    float ga = s_scal[1], gw = s_scal[2];
    float sS[R] = {0, 0, 0, 0}, sT[R] = {0, 0, 0, 0};
    for (int ii = 0; ii < 2; ii++) {
        int a = tid + ii * 512;
        float wwv = gw * (ga * s_tmp[a] + (1.f - ga) * s_cw[a]);
        g_ww[b][a] = wwv;
        float pp = prec_prev[b * A + a];
#pragma unroll
        for (int r = 0; r < R; r++) {
            float rw = rw_prev[(b * R + r) * A + a];
            sS[r] = fmaf(pp, rw, sS[r]);
            sT[r] = fmaf(wwv, rw, sT[r]);
        }
    }
#pragma unroll
    for (int r = 0; r < R; r++) {
        float v = blockSum<512>(sS[r], s_red);
        if (tid == 0) g_S[b][r] = v;
        v = blockSum<512>(sT[r], s_red);
        if (tid == 0) g_T[b][r] = v;
    }
}

// ----------------- K5: memory write + c_r content logits -----------------
__global__ void k5_mem_cr(const float* __restrict__ mem_prev) {
    int b = blockIdx.y, chunk = blockIdx.x;  // 8 chunks of 128 rows
    int tid = threadIdx.x;                   // 256 = 8 warps
    int warp = tid >> 5, lane = tid & 31;
    __shared__ float s_kr[R][M];
    __shared__ float s_er[M], s_wv[M];
    __shared__ float s_beta[R], s_kn[R];
    {
        int r = tid >> 6, m = tid & 63;
        s_kr[r][m] = g_iface[b][OFF_KR + r * M + m];
    }
    if (tid < M) s_er[tid] = sigf(g_iface[b][OFF_ERASE + tid]);
    else if (tid < 2 * M) s_wv[tid - M] = g_iface[b][OFF_WRITEV + (tid - M)];
    __syncthreads();
    if (tid < R) {
        s_beta[tid] = oneplusf(g_iface[b][OFF_BETAR + tid]);
        float s = 0.f;
#pragma unroll
        for (int m = 0; m < M; m++) { float v = s_kr[tid][m]; s = fmaf(v, v, s); }
        s_kn[tid] = sqrtf(s);
    }
    __syncthreads();

    for (int rr = 0; rr < 16; rr++) {
        int a = chunk * 128 + warp * 16 + rr;
        float w = g_ww[b][a];
        int m0 = lane * 2;
        const float2 v = *reinterpret_cast<const float2*>(
            mem_prev + ((size_t)(b * A + a)) * M + m0);
        float n0 = v.x * (1.f - w * s_er[m0]) + w * s_wv[m0];
        float n1 = v.y * (1.f - w * s_er[m0 + 1]) + w * s_wv[m0 + 1];
        *reinterpret_cast<float2*>(&g_mem[b][a][m0]) = make_float2(n0, n1);
        float nn = n0 * n0 + n1 * n1;
        float d[R];
#pragma unroll
        for (int r = 0; r < R; r++) d[r] = n0 * s_kr[r][m0] + n1 * s_kr[r][m0 + 1];
#pragma unroll
        for (int o = 16; o; o >>= 1) {
            nn += __shfl_down_sync(0xffffffffu, nn, o);
#pragma unroll
            for (int r = 0; r < R; r++) d[r] += __shfl_down_sync(0xffffffffu, d[r], o);
        }
        if (lane == 0) {
            float mn = sqrtf(nn);
#pragma unroll
            for (int r = 0; r < R; r++)
                g_cr[b][r][a] = s_beta[r] * d[r] / (s_kn[r] * mn + 1e-6f);
        }
    }
}

// ----------------- K6: softmax of c_r logits over A -----------------
__global__ void k6_crsm() {
    int b = blockIdx.x >> 2, r = blockIdx.x & 3;
    float* row = g_cr[b][r];
    int tid = threadIdx.x;  // 256
    __shared__ float s_red[16];
    float l[4];
    float mx = -1e30f;
#pragma unroll
    for (int i2 = 0; i2 < 4; i2++) { l[i2] = row[tid + i2 * 256]; mx = fmaxf(mx, l[i2]); }
    mx = blockMax<256>(mx, s_red);
    float s = 0.f;
#pragma unroll
    for (int i2 = 0; i2 < 4; i2++) { l[i2] = __expf(l[i2] - mx); s += l[i2]; }
    s = blockSum<256>(s, s_red);
    float inv = 1.f / s;
#pragma unroll
    for (int i2 = 0; i2 < 4; i2++) row[tid + i2 * 256] = l[i2] * inv;
}

// ----------------- K7: fused link pass — P,Q (rows) + U,V partials (cols) -----------------
__global__ void k7_link(const float* __restrict__ link_prev, const float* __restrict__ rw_prev) {
    int b = blockIdx.y, stripe = blockIdx.x;  // 8 stripes of 128 rows
    int tid = threadIdx.x;                    // 256
    __shared__ float4 s_rw4[A];   // rw[r=0..3][a]
    __shared__ float4 s_wr4[A];   // ww[a]*rw[r][a]
    for (int a = tid; a < A; a += 256) {
        float w = g_ww[b][a];
        float4 rv4;
        rv4.x = rw_prev[(b * R + 0) * A + a];
        rv4.y = rw_prev[(b * R + 1) * A + a];
        rv4.z = rw_prev[(b * R + 2) * A + a];
        rv4.w = rw_prev[(b * R + 3) * A + a];
        s_rw4[a] = rv4;
        s_wr4[a] = make_float4(rv4.x * w, rv4.y * w, rv4.z * w, rv4.w * w);
    }
    __syncthreads();
    const float* Lp = link_prev + (size_t)b * A * A;
    int jbase = stripe * 128;

    // Phase A: column partials U,V for all 1024 columns over the 128 stripe rows
    float u[4][R], v[4][R];
#pragma unroll
    for (int cc = 0; cc < 4; cc++)
#pragma unroll
        for (int r = 0; r < R; r++) { u[cc][r] = 0.f; v[cc][r] = 0.f; }
#pragma unroll 2
    for (int j = 0; j < 128; j++) {
        const float* Lr = Lp + (size_t)(jbase + j) * A;
        float4 rwj = s_rw4[jbase + j];
        float4 wrj = s_wr4[jbase + j];
#pragma unroll
        for (int cc = 0; cc < 4; cc++) {
            float val = Lr[tid + cc * 256];
            u[cc][0] = fmaf(val, rwj.x, u[cc][0]);
            u[cc][1] = fmaf(val, rwj.y, u[cc][1]);
            u[cc][2] = fmaf(val, rwj.z, u[cc][2]);
            u[cc][3] = fmaf(val, rwj.w, u[cc][3]);
            v[cc][0] = fmaf(val, wrj.x, v[cc][0]);
            v[cc][1] = fmaf(val, wrj.y, v[cc][1]);
            v[cc][2] = fmaf(val, wrj.z, v[cc][2]);
            v[cc][3] = fmaf(val, wrj.w, v[cc][3]);
        }
    }
#pragma unroll
    for (int cc = 0; cc < 4; cc++)
#pragma unroll
        for (int r = 0; r < R; r++) {
            g_Up[stripe][b][r][tid + cc * 256] = u[cc][r];
            g_Vp[stripe][b][r][tid + cc * 256] = v[cc][r];
        }

    // Phase B: full row dots P,Q for the 128 stripe rows (re-read stripe from L2)
    int rowl = tid >> 1, half = tid & 1;
    const float* Lr = Lp + (size_t)(jbase + rowl) * A + half * 512;
    float p[R] = {0, 0, 0, 0}, q[R] = {0, 0, 0, 0};
#pragma unroll 4
    for (int c = 0; c < 512; c += 4) {
        float4 val = *reinterpret_cast<const float4*>(Lr + c);
        int col = half * 512 + c;
        float4 r0 = s_rw4[col], r1 = s_rw4[col + 1], r2 = s_rw4[col + 2], r3 = s_rw4[col + 3];
        float4 w0 = s_wr4[col], w1 = s_wr4[col + 1], w2 = s_wr4[col + 2], w3 = s_wr4[col + 3];
        p[0] += val.x * r0.x + val.y * r1.x + val.z * r2.x + val.w * r3.x;
        p[1] += val.x * r0.y + val.y * r1.y + val.z * r2.y + val.w * r3.y;
        p[2] += val.x * r0.z + val.y * r1.z + val.z * r2.z + val.w * r3.z;
        p[3] += val.x * r0.w + val.y * r1.w + val.z * r2.w + val.w * r3.w;
        q[0] += val.x * w0.x + val.y * w1.x + val.z * w2.x + val.w * w3.x;
        q[1] += val.x * w0.y + val.y * w1.y + val.z * w2.y + val.w * w3.y;
        q[2] += val.x * w0.z + val.y * w1.z + val.z * w2.z + val.w * w3.z;
        q[3] += val.x * w0.w + val.y * w1.w + val.z * w2.w + val.w * w3.w;
    }
#pragma unroll
    for (int r = 0; r < R; r++) {
        p[r] += __shfl_xor_sync(0xffffffffu, p[r], 1);
        q[r] += __shfl_xor_sync(0xffffffffu, q[r], 1);
    }
    if (half == 0) {
        int row = jbase + rowl;
#pragma unroll
        for (int r = 0; r < R; r++) {
            g_P[b][r][row] = p[r];
            g_Q[b][r][row] = q[r];
        }
    }
}

// ----------------- K8: read weights + partial read vectors -----------------
__global__ void k8_wr_rv(const float* __restrict__ rw_prev, const float* __restrict__ prec_prev) {
    int b = blockIdx.y, chunk = blockIdx.x;  // 4 chunks of 256 slots
    int tid = threadIdx.x;                   // 256
    __shared__ float s_wr[R][256];
    __shared__ float s_pi[R][3];
    if (tid < R) {
        float l0 = g_iface[b][OFF_PI + tid * 3 + 0];
        float l1 = g_iface[b][OFF_PI + tid * 3 + 1];
        float l2 = g_iface[b][OFF_PI + tid * 3 + 2];
        float mx = fmaxf(l0, fmaxf(l1, l2));
        float e0 = __expf(l0 - mx), e1 = __expf(l1 - mx), e2 = __expf(l2 - mx);
        float inv = 1.f / (e0 + e1 + e2);
        s_pi[tid][0] = e0 * inv; s_pi[tid][1] = e1 * inv; s_pi[tid][2] = e2 * inv;
    }
    __syncthreads();
    int a = chunk * 256 + tid;
    float ww = g_ww[b][a];
    float pp = prec_prev[b * A + a];
#pragma unroll
    for (int r = 0; r < R; r++) {
        float rw = rw_prev[(b * R + r) * A + a];
        float P = g_P[b][r][a], Q = g_Q[b][r][a];
        float U = 0.f, V = 0.f;
#pragma unroll
        for (int s8 = 0; s8 < 8; s8++) {
            U += g_Up[s8][b][r][a];
            V += g_Vp[s8][b][r][a];
        }
        float Sr = g_S[b][r], Tr = g_T[b][r];
        float fwd = (1.f - ww) * P - Q + ww * (Sr - pp * rw);
        float bwd = (1.f - ww) * U - V + pp * (Tr - ww * rw);
        float cr = g_cr[b][r][a];
        s_wr[r][tid] = s_pi[r][0] * bwd + s_pi[r][1] * cr + s_pi[r][2] * fwd;
    }
    __syncthreads();
    int r = tid >> 6, m = tid & 63;
    float acc = 0.f;
    const float* memb = &g_mem[b][chunk * 256][0];
#pragma unroll 4
    for (int aa = 0; aa < 256; aa++) acc = fmaf(s_wr[r][aa], memb[(size_t)aa * M + m], acc);
    g_rvpart[chunk][b][r * M + m] = acc;
}

// ----------------- K9: final output projection -----------------
__global__ void k9_out(const float* __restrict__ W_rd, const float* __restrict__ b_rd,
                       float* __restrict__ out) {
    int b = blockIdx.x;
    int tid = threadIdx.x;  // 256
    __shared__ float s_rv[R * M];
    s_rv[tid] = g_rvpart[0][b][tid] + g_rvpart[1][b][tid] + g_rvpart[2][b][tid] +
                g_rvpart[3][b][tid];
    __syncthreads();
    float acc = g_outhid[b][tid] + b_rd[tid];
#pragma unroll 8
    for (int j = 0; j < R * M; j++) acc = fmaf(s_rv[j], W_rd[(size_t)j * O_OUT + tid], acc);
    out[b * O_OUT + tid] = acc;
}

// ----------------- launch -----------------
extern "C" void kernel_launch(void* const* d_in, const int* in_sizes, int n_in,
                              void* d_out, int out_size) {
    (void)in_sizes; (void)n_in; (void)out_size;
    const float* x          = (const float*)d_in[0];
    const float* h_prev     = (const float*)d_in[1];
    const float* c_prev     = (const float*)d_in[2];
    const float* mem_prev   = (const float*)d_in[3];
    const float* rw_prev    = (const float*)d_in[4];
    const float* ww_prev    = (const float*)d_in[5];
    const float* usage_prev = (const float*)d_in[6];
    const float* prec_prev  = (const float*)d_in[7];
    const float* link_prev  = (const float*)d_in[8];
    const float* rv_prev    = (const float*)d_in[9];
    const float* Wx         = (const float*)d_in[10];
    const float* Wh         = (const float*)d_in[11];
    const float* b_lstm     = (const float*)d_in[12];
    const float* W_hid      = (const float*)d_in[13];
    const float* b_hid      = (const float*)d_in[14];
    const float* W_if       = (const float*)d_in[15];
    const float* b_if       = (const float*)d_in[16];
    const float* W_rd       = (const float*)d_in[17];
    const float* b_rd       = (const float*)d_in[18];
    float* out = (float*)d_out;

    k1_zpart<<<dim3(8, 8), 256>>>(x, h_prev, rv_prev, Wx, Wh);
    k2_lstm<<<32, 256>>>(c_prev, b_lstm);
    k3_ifpart<<<dim3(46, 4), 256>>>(W_if, W_hid);
    k3b_ifsum<<<46, 256>>>(b_if, b_hid);
    k4a_cwlog<<<dim3(8, B), 256>>>(mem_prev);
    k4_alloc_ww<<<B, 512>>>(rw_prev, ww_prev, usage_prev, prec_prev);
    k5_mem_cr<<<dim3(8, B), 256>>>(mem_prev);
    k6_crsm<<<B * R, 256>>>();
    k7_link<<<dim3(8, B), 256>>>(link_prev, rw_prev);
    k8_wr_rv<<<dim3(4, B), 256>>>(rw_prev, prec_prev);
    k9_out<<<B, 256>>>(W_rd, b_rd, out);
}